// round 16
// baseline (speedup 1.0000x reference)
#include <cuda_runtime.h>
#include <cuda_bf16.h>
#include <cstdint>

#define N_VOX 262144
#define HCH   64
#define KOFF  27
#define TILE_M 128
#define NT     256

#define WROW     72                    // padded W^T row: 72 bf16 = 144 B
#define WTILE_EL (HCH * WROW)          // 4608 elems per split tile
#define WTILE_B  (WTILE_EL * 2)        // 9216 B
#define WOFF_B   (2 * WTILE_B)         // 18432 B per offset (hi + lo)

// ---------------- device globals (no allocs allowed) ----------------
// Packed hi/lo bf16 features: pk[row*32 + j] = {bf16x2 hi(2j,2j+1), bf16x2 lo}
// Row N_VOX is the zero sentinel row.
__device__ __align__(16) uint2 g_pkx[(size_t)(N_VOX + 1) * 32];
__device__ __align__(16) uint2 g_pkm[(size_t)(N_VOX + 1) * 32];
__device__ __align__(16) __nv_bfloat16 g_Wt[2][KOFF][2][WTILE_EL];

// ---------------- helpers ----------------
__device__ __forceinline__ uint32_t smem_u32(const void* p) {
    return (uint32_t)__cvta_generic_to_shared(p);
}
__device__ __forceinline__ void cp_async16(uint32_t dst, const void* src) {
    asm volatile("cp.async.ca.shared.global [%0], [%1], 16;" :: "r"(dst), "l"(src));
}
__device__ __forceinline__ void cp_commit() { asm volatile("cp.async.commit_group;"); }
__device__ __forceinline__ void cp_wait0()  { asm volatile("cp.async.wait_group 0;"); }

__device__ __forceinline__ void ldmx4(uint32_t* r, uint32_t addr) {
    asm volatile("ldmatrix.sync.aligned.m8n8.x4.shared.b16 {%0,%1,%2,%3}, [%4];"
                 : "=r"(r[0]), "=r"(r[1]), "=r"(r[2]), "=r"(r[3]) : "r"(addr));
}
__device__ __forceinline__ void mma16816(float* c, const uint32_t* a,
                                         uint32_t b0, uint32_t b1) {
    asm volatile("mma.sync.aligned.m16n8k16.row.col.f32.bf16.bf16.f32 "
                 "{%0,%1,%2,%3}, {%4,%5,%6,%7}, {%8,%9}, {%0,%1,%2,%3};"
                 : "+f"(c[0]), "+f"(c[1]), "+f"(c[2]), "+f"(c[3])
                 : "r"(a[0]), "r"(a[1]), "r"(a[2]), "r"(a[3]), "r"(b0), "r"(b1));
}

// ---------------- W prep: W[k][kin][n] -> W^T[n][kin], hi/lo split, 144B rows
__global__ void prep_w(const float* __restrict__ Wa, const float* __restrict__ Wb) {
    int i = blockIdx.x * blockDim.x + threadIdx.x;
    const int total = KOFF * HCH * HCH;
    if (i >= 2 * total) return;
    const int w = i / total;
    const int r = i - w * total;           // k*4096 + kin*64 + n
    const float v = (w == 0) ? Wa[r] : Wb[r];
    const int k   = r >> 12;
    const int kin = (r >> 6) & 63;
    const int n   = r & 63;
    __nv_bfloat16 hi = __float2bfloat16(v);
    __nv_bfloat16 lo = __float2bfloat16(v - __bfloat162float(hi));
    g_Wt[w][k][0][n * WROW + kin] = hi;
    g_Wt[w][k][1][n * WROW + kin] = lo;
}

// ---------------- x prep: fp32 -> packed hi/lo bf16; also zero sentinel rows
__global__ void prep_x(const float* __restrict__ x) {
    const size_t i = (size_t)blockIdx.x * blockDim.x + threadIdx.x;
    const size_t total = (size_t)(N_VOX + 1) * 32;
    if (i >= total) return;
    uint2 o = make_uint2(0u, 0u);
    if (i < (size_t)N_VOX * 32) {
        const float2 v = ((const float2*)x)[i];
        __nv_bfloat162 h = __floats2bfloat162_rn(v.x, v.y);
        __nv_bfloat162 l = __floats2bfloat162_rn(v.x - __bfloat162float(h.x),
                                                 v.y - __bfloat162float(h.y));
        o.x = *(uint32_t*)&h;
        o.y = *(uint32_t*)&l;
        g_pkx[i] = o;
    } else {
        g_pkx[i] = o;
        g_pkm[i] = o;      // zero sentinel row of mid as well
    }
}

// ---------------- main conv kernel: 8 warps, m16/warp, HMMA ----------------
__global__ void __launch_bounds__(NT, 2)
spconv_mma(const uint2* __restrict__ pk,               // packed hi/lo feats
           const __nv_bfloat16* __restrict__ wt,       // [KOFF][2][WTILE_EL]
           const int* __restrict__ nbr,
           const float* __restrict__ resid,            // conv_b only
           float* __restrict__ outf,                   // conv_b only
           uint2* __restrict__ outpk)                  // conv_a only (relu+pack)
{
    __shared__ __align__(16) char wbuf[2][WOFF_B];

    const int t    = threadIdx.x;
    const int w    = t >> 5;                        // 0..7, one m16 tile each
    const int lane = t & 31;
    const int row0 = blockIdx.x * TILE_M;
    const int gr   = row0 + 16 * w + (lane >> 2);   // fragment base row

    const uint32_t sb[2] = { smem_u32(wbuf[0]), smem_u32(wbuf[1]) };
    const int q = lane >> 3, e = lane & 7;
    const uint32_t lm_lane = (uint32_t)(((q & 1) * 8 + e) * 144 + (q >> 1) * 16);
    const int jlane = lane & 3;                     // pair-column within fragment

    const char* pkb  = (const char*)pk;
    const char* nbrb = (const char*)nbr;

    float acc[8][4];
#pragma unroll
    for (int j = 0; j < 8; ++j)
#pragma unroll
        for (int c = 0; c < 4; ++c) acc[j][c] = 0.0f;

    // 32-bit byte offsets everywhere (pk is 64MB, nbr 28MB: fits u32)
    uint32_t idxc[2], idxn[2];
#define LOAD_IDX(dst, kk) do { \
        dst[0] = (uint32_t)__ldg((const int*)(nbrb + ((uint32_t)(gr)     * KOFF + (kk)) * 4u)); \
        dst[1] = (uint32_t)__ldg((const int*)(nbrb + ((uint32_t)(gr + 8) * KOFF + (kk)) * 4u)); } while (0)

    // A fragments (hi+lo splits) for one 16-wide k-chunk, direct from pk.
#define LOAD_APK(Ah, Al, idx, kc) do { \
        const uint32_t jb = ((uint32_t)(kc) * 8 + (uint32_t)jlane) * 8u; \
        _Pragma("unroll") \
        for (int h = 0; h < 2; ++h) { \
            const uint32_t off = idx[h] * 256u + jb; \
            const uint2 g0 = __ldg((const uint2*)(pkb + off)); \
            const uint2 g1 = __ldg((const uint2*)(pkb + off + 32u)); \
            (Ah)[h]     = g0.x;  (Al)[h]     = g0.y; \
            (Ah)[2 + h] = g1.x;  (Al)[2 + h] = g1.y; \
        } } while (0)

    // ---- prologue: stage W[0], load idx + A(k=0,kc=0)
    {
        const char* src = (const char*)wt;
        for (int i = t; i < WOFF_B / 16; i += NT)
            cp_async16(sb[0] + i * 16, src + i * 16);
        cp_commit();
    }
    LOAD_IDX(idxc, 0);
    uint32_t Ah[2][4], Al[2][4];        // ping-pong fragment buffers (kc&1)
    LOAD_APK(Ah[0], Al[0], idxc, 0);
    cp_wait0();
    __syncthreads();

#pragma unroll 1
    for (int k = 0; k < KOFF; ++k) {
        const int b = k & 1;
        if (k < KOFF - 1) {
            const char* src = (const char*)wt + (size_t)(k + 1) * WOFF_B;
            for (int i = t; i < WOFF_B / 16; i += NT)
                cp_async16(sb[b ^ 1] + i * 16, src + i * 16);
            cp_commit();
            LOAD_IDX(idxn, k + 1);
        }
        const uint32_t sbuf = sb[b];

#pragma unroll
        for (int kc = 0; kc < 4; ++kc) {
            const int cur = kc & 1, nxt = cur ^ 1;
            // prefetch next A chunk BEFORE consuming current
            if (kc < 3)              { LOAD_APK(Ah[nxt], Al[nxt], idxc, kc + 1); }
            else if (k < KOFF - 1)   { LOAD_APK(Ah[nxt], Al[nxt], idxn, 0); }

            uint32_t B[16];
            const uint32_t a0 = sbuf + (uint32_t)(kc * 32) + lm_lane;
            // --- W_hi fragments: used by Ah and Al combos
#pragma unroll
            for (int u = 0; u < 4; ++u)
                ldmx4(&B[u * 4], a0 + (uint32_t)(u * 16 * 144));
#pragma unroll
            for (int j = 0; j < 8; ++j) {
                const int u4 = (j >> 1) * 4 + (j & 1);
                mma16816(acc[j], Ah[cur], B[u4], B[u4 + 2]);
                mma16816(acc[j], Al[cur], B[u4], B[u4 + 2]);
            }
            // --- W_lo fragments: reuse the same registers
#pragma unroll
            for (int u = 0; u < 4; ++u)
                ldmx4(&B[u * 4], a0 + (uint32_t)(u * 16 * 144) + WTILE_B);
#pragma unroll
            for (int j = 0; j < 8; ++j) {
                const int u4 = (j >> 1) * 4 + (j & 1);
                mma16816(acc[j], Ah[cur], B[u4], B[u4 + 2]);
            }
        }

        if (k < KOFF - 1) cp_wait0();
        __syncthreads();
        idxc[0] = idxn[0]; idxc[1] = idxn[1];
    }

    // ---- epilogue ----
    if (outpk) {
        // conv_a: relu, split to hi/lo, packed store (feeds conv_b's gather)
#pragma unroll
        for (int half = 0; half < 2; ++half) {
            const uint32_t row = (uint32_t)(gr + 8 * half);
#pragma unroll
            for (int j = 0; j < 8; ++j) {
                float v0 = fmaxf(acc[j][half * 2 + 0], 0.f);
                float v1 = fmaxf(acc[j][half * 2 + 1], 0.f);
                __nv_bfloat162 h = __floats2bfloat162_rn(v0, v1);
                __nv_bfloat162 l = __floats2bfloat162_rn(v0 - __bfloat162float(h.x),
                                                         v1 - __bfloat162float(h.y));
                outpk[row * 32u + j * 4 + jlane] =
                    make_uint2(*(uint32_t*)&h, *(uint32_t*)&l);
            }
        }
    } else {
        // conv_b: residual add, fp32 store
#pragma unroll
        for (int half = 0; half < 2; ++half) {
            const uint32_t row = (uint32_t)(gr + 8 * half);
#pragma unroll
            for (int j = 0; j < 8; ++j) {
                const int c = j * 8 + jlane * 2;
                float v0 = acc[j][half * 2 + 0];
                float v1 = acc[j][half * 2 + 1];
                const float2 r = *(const float2*)(resid + (size_t)row * HCH + c);
                v0 += r.x; v1 += r.y;
                *(float2*)(outf + (size_t)row * HCH + c) = make_float2(v0, v1);
            }
        }
    }
}

// ---------------- launch ----------------
extern "C" void kernel_launch(void* const* d_in, const int* in_sizes, int n_in,
                              void* d_out, int out_size)
{
    const float* x   = (const float*)d_in[0];   // [N, 64]
    const float* Wa  = (const float*)d_in[1];   // [27, 64, 64]
    const float* Wb  = (const float*)d_in[2];   // [27, 64, 64]
    const int*   nbr = (const int*)d_in[3];     // [N, 27]
    float* out = (float*)d_out;

    uint2 *pkx = nullptr, *pkm = nullptr;
    __nv_bfloat16* wt = nullptr;
    cudaGetSymbolAddress((void**)&pkx, g_pkx);
    cudaGetSymbolAddress((void**)&pkm, g_pkm);
    cudaGetSymbolAddress((void**)&wt, g_Wt);

    const int totalw = 2 * KOFF * HCH * HCH;
    prep_w<<<(totalw + 255) / 256, 256>>>(Wa, Wb);

    const size_t totalx = (size_t)(N_VOX + 1) * 32;
    prep_x<<<(int)((totalx + 255) / 256), 256>>>(x);

    const int grid = N_VOX / TILE_M;   // 2048
    const size_t wstride = (size_t)KOFF * 2 * WTILE_EL;
    // conv_a + ReLU -> packed mid
    spconv_mma<<<grid, NT>>>(pkx, wt, nbr, nullptr, nullptr, pkm);
    // conv_b + residual -> out
    spconv_mma<<<grid, NT>>>(pkm, wt + wstride, nbr, x, out, nullptr);
}

// round 17
// speedup vs baseline: 1.2585x; 1.2585x over previous
#include <cuda_runtime.h>
#include <cuda_fp16.h>
#include <cstdint>

#define N_VOX 262144
#define HCH   64
#define KOFF  27
#define TILE_M 128
#define NT     128

#define WROW     72                    // padded W^T row: 72 fp16 = 144 B
#define WTILE_EL (HCH * WROW)          // 4608 elems per offset tile
#define WTILE_B  (WTILE_EL * 2)        // 9216 B per offset (hi only)

// ---------------- device globals (no allocs allowed) ----------------
// Packed hi/lo fp16 features: pk[row*32 + j] = {fp16x2 hi(2j,2j+1), fp16x2 lo}
// Row N_VOX is the zero sentinel row.
__device__ __align__(16) uint2 g_pkx[(size_t)(N_VOX + 1) * 32];
__device__ __align__(16) uint2 g_pkm[(size_t)(N_VOX + 1) * 32];
__device__ __align__(16) __half g_Wt[2][KOFF][WTILE_EL];

// ---------------- helpers ----------------
__device__ __forceinline__ uint32_t smem_u32(const void* p) {
    return (uint32_t)__cvta_generic_to_shared(p);
}
__device__ __forceinline__ void cp_async16(uint32_t dst, const void* src) {
    asm volatile("cp.async.ca.shared.global [%0], [%1], 16;" :: "r"(dst), "l"(src));
}
__device__ __forceinline__ void cp_commit() { asm volatile("cp.async.commit_group;"); }
__device__ __forceinline__ void cp_wait0()  { asm volatile("cp.async.wait_group 0;"); }

__device__ __forceinline__ void ldmx4(uint32_t* r, uint32_t addr) {
    asm volatile("ldmatrix.sync.aligned.m8n8.x4.shared.b16 {%0,%1,%2,%3}, [%4];"
                 : "=r"(r[0]), "=r"(r[1]), "=r"(r[2]), "=r"(r[3]) : "r"(addr));
}
__device__ __forceinline__ void mma16816(float* c, const uint32_t* a,
                                         uint32_t b0, uint32_t b1) {
    asm volatile("mma.sync.aligned.m16n8k16.row.col.f32.f16.f16.f32 "
                 "{%0,%1,%2,%3}, {%4,%5,%6,%7}, {%8,%9}, {%0,%1,%2,%3};"
                 : "+f"(c[0]), "+f"(c[1]), "+f"(c[2]), "+f"(c[3])
                 : "r"(a[0]), "r"(a[1]), "r"(a[2]), "r"(a[3]), "r"(b0), "r"(b1));
}

// ---------------- W prep: W[k][kin][n] -> W^T[n][kin] fp16, 144B rows ------
__global__ void prep_w(const float* __restrict__ Wa, const float* __restrict__ Wb) {
    int i = blockIdx.x * blockDim.x + threadIdx.x;
    const int total = KOFF * HCH * HCH;
    if (i >= 2 * total) return;
    const int w = i / total;
    const int r = i - w * total;           // k*4096 + kin*64 + n
    const float v = (w == 0) ? Wa[r] : Wb[r];
    const int k   = r >> 12;
    const int kin = (r >> 6) & 63;
    const int n   = r & 63;
    g_Wt[w][k][n * WROW + kin] = __float2half_rn(v);
}

// ---------------- x prep: fp32 -> packed hi/lo fp16; zero sentinel rows ----
__global__ void prep_x(const float* __restrict__ x) {
    const size_t i = (size_t)blockIdx.x * blockDim.x + threadIdx.x;
    const size_t total = (size_t)(N_VOX + 1) * 32;
    if (i >= total) return;
    uint2 o = make_uint2(0u, 0u);
    if (i < (size_t)N_VOX * 32) {
        const float2 v = ((const float2*)x)[i];
        const __half hx = __float2half_rn(v.x);
        const __half hy = __float2half_rn(v.y);
        const __half lx = __float2half_rn(v.x - __half2float(hx));
        const __half ly = __float2half_rn(v.y - __half2float(hy));
        __half2 h = __halves2half2(hx, hy);
        __half2 l = __halves2half2(lx, ly);
        o.x = *(uint32_t*)&h;
        o.y = *(uint32_t*)&l;
        g_pkx[i] = o;
    } else {
        g_pkx[i] = o;
        g_pkm[i] = o;      // zero sentinel row of mid as well
    }
}

// ---------------- main conv kernel: 4 warps, m32/warp, fp16 2-MMA ----------
__global__ void __launch_bounds__(NT, 4)
spconv_mma(const uint2* __restrict__ pk,               // packed hi/lo feats
           const __half* __restrict__ wt,              // [KOFF][WTILE_EL]
           const int* __restrict__ nbr,
           const float* __restrict__ resid,            // conv_b only
           float* __restrict__ outf,                   // conv_b only
           uint2* __restrict__ outpk)                  // conv_a only (relu+pack)
{
    __shared__ __align__(16) char wbuf[2][WTILE_B];

    const int t    = threadIdx.x;
    const int w    = t >> 5;                        // 0..3, one m32 slab each
    const int lane = t & 31;
    const int row0 = blockIdx.x * TILE_M;
    const int gr   = row0 + 32 * w + (lane >> 2);   // fragment base row

    const uint32_t sb[2] = { smem_u32(wbuf[0]), smem_u32(wbuf[1]) };
    const int q = lane >> 3, e = lane & 7;
    const uint32_t lm_lane = (uint32_t)(((q & 1) * 8 + e) * 144 + (q >> 1) * 16);
    const int jlane = lane & 3;                     // pair-column within fragment

    const char* pkb  = (const char*)pk;
    const char* nbrb = (const char*)nbr;

    float acc[2][8][4];
#pragma unroll
    for (int a = 0; a < 2; ++a)
#pragma unroll
        for (int j = 0; j < 8; ++j)
#pragma unroll
            for (int c = 0; c < 4; ++c) acc[a][j][c] = 0.0f;

    uint32_t idxc[4], idxn[4];
#define LOAD_IDX(dst, kk) do { \
        dst[0] = (uint32_t)__ldg((const int*)(nbrb + ((uint32_t)(gr)      * KOFF + (kk)) * 4u)); \
        dst[1] = (uint32_t)__ldg((const int*)(nbrb + ((uint32_t)(gr + 8)  * KOFF + (kk)) * 4u)); \
        dst[2] = (uint32_t)__ldg((const int*)(nbrb + ((uint32_t)(gr + 16) * KOFF + (kk)) * 4u)); \
        dst[3] = (uint32_t)__ldg((const int*)(nbrb + ((uint32_t)(gr + 24) * KOFF + (kk)) * 4u)); } while (0)

    // A fragments (hi+lo splits), 2 m16 tiles, one 16-wide k-chunk.
#define LOAD_APK(Ah, Al, idx, kc) do { \
        const uint32_t jb = ((uint32_t)(kc) * 8 + (uint32_t)jlane) * 8u; \
        _Pragma("unroll") \
        for (int tt = 0; tt < 2; ++tt) { \
            _Pragma("unroll") \
            for (int h = 0; h < 2; ++h) { \
                const uint32_t off = idx[tt * 2 + h] * 256u + jb; \
                const uint2 g0 = __ldg((const uint2*)(pkb + off)); \
                const uint2 g1 = __ldg((const uint2*)(pkb + off + 32u)); \
                (Ah)[tt][h]     = g0.x;  (Al)[tt][h]     = g0.y; \
                (Ah)[tt][2 + h] = g1.x;  (Al)[tt][2 + h] = g1.y; \
            } \
        } } while (0)

    // ---- prologue: stage W[0], load idx + A(k=0,kc=0)
    {
        const char* src = (const char*)wt;
        for (int i = t; i < WTILE_B / 16; i += NT)
            cp_async16(sb[0] + i * 16, src + i * 16);
        cp_commit();
    }
    LOAD_IDX(idxc, 0);
    uint32_t Ah[2][2][4], Al[2][2][4];   // [buf][tt][frag], buf toggles with kc
    LOAD_APK(Ah[0], Al[0], idxc, 0);
    cp_wait0();
    __syncthreads();

#pragma unroll 1
    for (int k = 0; k < KOFF; ++k) {
        const int b = k & 1;
        if (k < KOFF - 1) {
            const char* src = (const char*)wt + (size_t)(k + 1) * WTILE_B;
            for (int i = t; i < WTILE_B / 16; i += NT)
                cp_async16(sb[b ^ 1] + i * 16, src + i * 16);
            cp_commit();
            LOAD_IDX(idxn, k + 1);
        }
        const uint32_t sbuf = sb[b];

#pragma unroll
        for (int kc = 0; kc < 4; ++kc) {
            const int cur = kc & 1, nxt = cur ^ 1;
            // prefetch next A chunk BEFORE consuming current
            if (kc < 3)              { LOAD_APK(Ah[nxt], Al[nxt], idxc, kc + 1); }
            else if (k < KOFF - 1)   { LOAD_APK(Ah[nxt], Al[nxt], idxn, 0); }

            const uint32_t a0 = sbuf + (uint32_t)(kc * 32) + lm_lane;
            // B held in only 4 regs: each ldmx4 feeds 8 MMAs immediately
#pragma unroll
            for (int u = 0; u < 4; ++u) {
                uint32_t B[4];
                ldmx4(B, a0 + (uint32_t)(u * 16 * 144));
#pragma unroll
                for (int tt = 0; tt < 2; ++tt) {
                    mma16816(acc[tt][u * 2 + 0], Ah[cur][tt], B[0], B[2]);
                    mma16816(acc[tt][u * 2 + 0], Al[cur][tt], B[0], B[2]);
                    mma16816(acc[tt][u * 2 + 1], Ah[cur][tt], B[1], B[3]);
                    mma16816(acc[tt][u * 2 + 1], Al[cur][tt], B[1], B[3]);
                }
            }
        }

        if (k < KOFF - 1) cp_wait0();
        __syncthreads();
        idxc[0] = idxn[0]; idxc[1] = idxn[1];
        idxc[2] = idxn[2]; idxc[3] = idxn[3];
    }

    // ---- epilogue ----
    if (outpk) {
        // conv_a: relu, fp16 hi/lo split, packed store (feeds conv_b's gather)
#pragma unroll
        for (int tt = 0; tt < 2; ++tt) {
#pragma unroll
            for (int half = 0; half < 2; ++half) {
                const uint32_t row = (uint32_t)(gr + 16 * tt + 8 * half);
#pragma unroll
                for (int j = 0; j < 8; ++j) {
                    float v0 = fmaxf(acc[tt][j][half * 2 + 0], 0.f);
                    float v1 = fmaxf(acc[tt][j][half * 2 + 1], 0.f);
                    const __half h0 = __float2half_rn(v0);
                    const __half h1 = __float2half_rn(v1);
                    const __half l0 = __float2half_rn(v0 - __half2float(h0));
                    const __half l1 = __float2half_rn(v1 - __half2float(h1));
                    __half2 h = __halves2half2(h0, h1);
                    __half2 l = __halves2half2(l0, l1);
                    outpk[row * 32u + j * 4 + jlane] =
                        make_uint2(*(uint32_t*)&h, *(uint32_t*)&l);
                }
            }
        }
    } else {
        // conv_b: residual add, fp32 store
#pragma unroll
        for (int tt = 0; tt < 2; ++tt) {
#pragma unroll
            for (int half = 0; half < 2; ++half) {
                const uint32_t row = (uint32_t)(gr + 16 * tt + 8 * half);
#pragma unroll
                for (int j = 0; j < 8; ++j) {
                    const int c = j * 8 + jlane * 2;
                    float v0 = acc[tt][j][half * 2 + 0];
                    float v1 = acc[tt][j][half * 2 + 1];
                    const float2 r = *(const float2*)(resid + (size_t)row * HCH + c);
                    v0 += r.x; v1 += r.y;
                    *(float2*)(outf + (size_t)row * HCH + c) = make_float2(v0, v1);
                }
            }
        }
    }
}

// ---------------- launch ----------------
extern "C" void kernel_launch(void* const* d_in, const int* in_sizes, int n_in,
                              void* d_out, int out_size)
{
    const float* x   = (const float*)d_in[0];   // [N, 64]
    const float* Wa  = (const float*)d_in[1];   // [27, 64, 64]
    const float* Wb  = (const float*)d_in[2];   // [27, 64, 64]
    const int*   nbr = (const int*)d_in[3];     // [N, 27]
    float* out = (float*)d_out;

    uint2 *pkx = nullptr, *pkm = nullptr;
    __half* wt = nullptr;
    cudaGetSymbolAddress((void**)&pkx, g_pkx);
    cudaGetSymbolAddress((void**)&pkm, g_pkm);
    cudaGetSymbolAddress((void**)&wt, g_Wt);

    const int totalw = 2 * KOFF * HCH * HCH;
    prep_w<<<(totalw + 255) / 256, 256>>>(Wa, Wb);

    const size_t totalx = (size_t)(N_VOX + 1) * 32;
    prep_x<<<(int)((totalx + 255) / 256), 256>>>(x);

    const int grid = N_VOX / TILE_M;   // 2048
    const size_t wstride = (size_t)KOFF * WTILE_EL;
    // conv_a + ReLU -> packed mid
    spconv_mma<<<grid, NT>>>(pkx, wt, nbr, nullptr, nullptr, pkm);
    // conv_b + residual -> out
    spconv_mma<<<grid, NT>>>(pkm, wt + wstride, nbr, x, out, nullptr);
}